// round 15
// baseline (speedup 1.0000x reference)
#include <cuda_runtime.h>
#include <cuda_bf16.h>
#include <cstdint>
#include <cstring>

#define N_NODES   100000
#define N_PAD     100032    // 1563 * 64
#define N_EDGES_MAX 1600000
#define N_GRAPHS  256
#define IN_DIM    205
#define HID_DIM   128
#define FC_DIM    64
#define OUT_DIM   2
#define SCAN_BLK  1024

#define CH    48    // K-chunk per smem stage (3 MMA k-steps)
#define KPS   56    // smem row stride in bf16 (112B = 7*16B)
#define KPW1  240   // padded K for layer-1 (5 chunks), 30 uint4/row
#define KPW2  144   // padded K for layer-2 (3 chunks), 18 uint4/row

#define NCK   4     // pipeline chunks
#define CBLK  391   // 64-row blocks per chunk (last = 390)

// ---------------- scratch (static device globals; referenced ONLY from device code) ----------------
__device__ __align__(128) float g_h1[(size_t)N_PAD * HID_DIM];
__device__ __align__(128) float g_h2[(size_t)N_PAD * HID_DIM];
__device__ __align__(128) uint32_t g_x1hi[(size_t)N_PAD * (KPW1 / 2)];
__device__ __align__(128) uint32_t g_x1lo[(size_t)N_PAD * (KPW1 / 2)];
__device__ __align__(128) uint32_t g_aghi[(size_t)N_PAD * (KPW2 / 2)];
__device__ __align__(128) uint32_t g_aglo[(size_t)N_PAD * (KPW2 / 2)];
__device__ int   g_degi[N_NODES];
__device__ int   g_rowstart[N_NODES];
__device__ int   g_cursor[N_NODES];
__device__ int   g_blocksum[128];
__device__ int   g_csrc[N_EDGES_MAX];
__device__ float g_ds[N_NODES];
__device__ float g_gsum[N_GRAPHS * HID_DIM];
__device__ float g_gcnt[N_GRAPHS];
__device__ __align__(128) __nv_bfloat16 g_w1hi[HID_DIM * KPW1];
__device__ __align__(128) __nv_bfloat16 g_w1lo[HID_DIM * KPW1];
__device__ __align__(128) __nv_bfloat16 g_w2hi[HID_DIM * KPW2];
__device__ __align__(128) __nv_bfloat16 g_w2lo[HID_DIM * KPW2];

// ---------------- helpers ----------------
__device__ __forceinline__ uint32_t sptr(const void* p) {
    return (uint32_t)__cvta_generic_to_shared(p);
}
__device__ __forceinline__ void ldsm4(uint32_t* r, uint32_t addr) {
    asm volatile("ldmatrix.sync.aligned.m8n8.x4.shared.b16 {%0,%1,%2,%3}, [%4];"
                 : "=r"(r[0]), "=r"(r[1]), "=r"(r[2]), "=r"(r[3]) : "r"(addr));
}
__device__ __forceinline__ void mma16816(float* d, const uint32_t* a, const uint32_t* b) {
    asm volatile("mma.sync.aligned.m16n8k16.row.col.f32.bf16.bf16.f32 "
                 "{%0,%1,%2,%3}, {%4,%5,%6,%7}, {%8,%9}, {%0,%1,%2,%3};"
                 : "+f"(d[0]), "+f"(d[1]), "+f"(d[2]), "+f"(d[3])
                 : "r"(a[0]), "r"(a[1]), "r"(a[2]), "r"(a[3]), "r"(b[0]), "r"(b[1]));
}
__device__ __forceinline__ void cpasync16(uint32_t dst, const void* src) {
    asm volatile("cp.async.cg.shared.global [%0], [%1], 16;" :: "r"(dst), "l"(src));
}
__device__ __forceinline__ uint32_t packbf(float a, float b) {
    return (uint32_t)__bfloat16_as_ushort(__float2bfloat16(a)) |
           ((uint32_t)__bfloat16_as_ushort(__float2bfloat16(b)) << 16);
}

// ---------------- zero the small accumulators ----------------
__global__ void zero_kernel() {
    int i = blockIdx.x * blockDim.x + threadIdx.x;
    if (i < N_NODES) g_degi[i] = 0;
    if (i < N_GRAPHS * HID_DIM) g_gsum[i] = 0.0f;
}

// ---------------- X split (row range): fp32 -> bf16 hi/lo pairs ----------------
__global__ void xsplit_kernel(const float* __restrict__ X, int r0, int nrows, int n) {
    int idx = blockIdx.x * blockDim.x + threadIdx.x;
    if (idx >= nrows * (KPW1 / 2)) return;
    int row = r0 + idx / (KPW1 / 2);
    int kp  = idx % (KPW1 / 2);
    if (row >= n) return;
    int k0 = kp * 2;
    float v0 = (k0 < IN_DIM) ? X[(size_t)row * IN_DIM + k0] : 0.0f;
    float v1 = (k0 + 1 < IN_DIM) ? X[(size_t)row * IN_DIM + k0 + 1] : 0.0f;
    __nv_bfloat16 h0 = __float2bfloat16(v0), h1 = __float2bfloat16(v1);
    size_t o = (size_t)row * (KPW1 / 2) + kp;
    g_x1hi[o] = (uint32_t)__bfloat16_as_ushort(h0) | ((uint32_t)__bfloat16_as_ushort(h1) << 16);
    g_x1lo[o] = packbf(v0 - __bfloat162float(h0), v1 - __bfloat162float(h1));
}

// ---------------- weight split ----------------
template <bool SECOND>
__global__ void wsplit_kernel(const float* __restrict__ W) {
    constexpr int K   = SECOND ? HID_DIM : IN_DIM;
    constexpr int KPW = SECOND ? KPW2 : KPW1;
    __nv_bfloat16* hi = SECOND ? g_w2hi : g_w1hi;
    __nv_bfloat16* lo = SECOND ? g_w2lo : g_w1lo;
    int idx = blockIdx.x * blockDim.x + threadIdx.x;
    if (idx >= KPW * HID_DIM) return;
    int kk = idx >> 7;
    int n  = idx & 127;
    float v = (kk < K) ? W[kk * HID_DIM + n] : 0.0f;
    __nv_bfloat16 h = __float2bfloat16(v);
    hi[n * KPW + kk] = h;
    lo[n * KPW + kk] = __float2bfloat16(v - __bfloat162float(h));
}

// ---------------- in-degree histogram ----------------
__global__ void hist_kernel(const int* __restrict__ dst, int E) {
    int e = blockIdx.x * blockDim.x + threadIdx.x;
    if (e < E) atomicAdd(&g_degi[dst[e]], 1);
}

// ---------------- scan level 1 ----------------
__global__ void scan1_kernel() {
    __shared__ int sh[SCAN_BLK];
    int i = blockIdx.x * SCAN_BLK + threadIdx.x;
    int v = (i < N_NODES) ? g_degi[i] : 0;
    sh[threadIdx.x] = v;
    __syncthreads();
    for (int off = 1; off < SCAN_BLK; off <<= 1) {
        int t = (threadIdx.x >= off) ? sh[threadIdx.x - off] : 0;
        __syncthreads();
        sh[threadIdx.x] += t;
        __syncthreads();
    }
    if (i < N_NODES) g_rowstart[i] = sh[threadIdx.x] - v;
    if (threadIdx.x == SCAN_BLK - 1) g_blocksum[blockIdx.x] = sh[threadIdx.x];
}

// -------- scan level 2 fused ----------------
__global__ void scan3_kernel(int nb) {
    __shared__ int pref[256];
    int t = threadIdx.x;
    int v = (t < nb) ? g_blocksum[t] : 0;
    pref[t] = v;
    __syncthreads();
    for (int off = 1; off < 256; off <<= 1) {
        int u = (t >= off) ? pref[t - off] : 0;
        __syncthreads();
        pref[t] += u;
        __syncthreads();
    }
    int ex = pref[t] - v;
    __syncthreads();
    pref[t] = ex;
    __syncthreads();

    int i = blockIdx.x * blockDim.x + t;
    if (i >= N_NODES) return;
    int rs = g_rowstart[i] + pref[i / SCAN_BLK];
    g_rowstart[i] = rs;
    g_cursor[i] = rs;
    g_ds[i] = rsqrtf((float)g_degi[i] + 1.0f);
}

// ---------------- graph node counts via binary search ----------------
__global__ void gcnt_kernel(const int* __restrict__ batch, int n) {
    __shared__ int lb[N_GRAPHS + 1];
    int g = threadIdx.x;
    int lo = 0, hi = n;
    while (lo < hi) {
        int mid = (lo + hi) >> 1;
        if (batch[mid] < g) lo = mid + 1; else hi = mid;
    }
    lb[g] = lo;
    if (g == 0) lb[N_GRAPHS] = n;
    __syncthreads();
    g_gcnt[g] = (float)(lb[g + 1] - lb[g]);
}

// ---------------- CSR scatter ----------------
__global__ void scatter_kernel(const int* __restrict__ src, const int* __restrict__ dst, int E) {
    int e = blockIdx.x * blockDim.x + threadIdx.x;
    if (e < E) {
        int pos = atomicAdd(&g_cursor[dst[e]], 1);
        g_csrc[pos] = src[e];
    }
}

// ---------------- split-bf16 MMA GEMM, cp.async double-buffered, row-chunked ----------------
template <int NCHUNK, int SRC_U4, bool PRE>
__global__ void __launch_bounds__(256) gemm_mma_kernel(int N, int rowbase) {
    extern __shared__ __align__(128) uint4 smem[];
    constexpr int XS_U4 = 64 * 7;
    constexpr int WS_U4 = 128 * 7;
    constexpr int STAGE_U4 = 2 * XS_U4 + 2 * WS_U4;

    const uint4* xin_hi = reinterpret_cast<const uint4*>(PRE ? g_aghi : g_x1hi);
    const uint4* xin_lo = reinterpret_cast<const uint4*>(PRE ? g_aglo : g_x1lo);
    const uint4* win_hi = reinterpret_cast<const uint4*>(PRE ? g_w2hi : g_w1hi);
    const uint4* win_lo = reinterpret_cast<const uint4*>(PRE ? g_w2lo : g_w1lo);
    float* OUT = PRE ? g_h2 : g_h1;

    int row0 = rowbase + blockIdx.x * 64;
    int tid  = threadIdx.x;
    int lane = tid & 31;
    int warp = tid >> 5;
    int warp_m = warp & 1;
    int warp_n = warp >> 1;
    int g = lane >> 2;
    int q = lane & 3;

    int a_row = warp_m * 32 + (lane & 7) + ((lane >> 3) & 1) * 8;
    int a_kof = ((lane >> 4) & 1) * 8;
    int b_row = warp_n * 32 + (lane & 7) + ((lane >> 4) & 1) * 8;
    int b_kof = ((lane >> 3) & 1) * 8;

    auto prefetch = [&](int c, int s) {
        uint4* base = smem + s * STAGE_U4;
        for (int idx = tid; idx < 768; idx += 256) {
            int row = idx / 12;
            int r2 = idx - row * 12;
            int arr = r2 / 6;
            int j = r2 - arr * 6;
            const uint4* src = (arr ? xin_lo : xin_hi) + (size_t)(row0 + row) * SRC_U4 + c * 6 + j;
            cpasync16(sptr(base + arr * XS_U4 + row * 7 + j), src);
        }
        for (int idx = tid; idx < 1536; idx += 256) {
            int row = idx / 12;
            int r2 = idx - row * 12;
            int arr = r2 / 6;
            int j = r2 - arr * 6;
            const uint4* src = (arr ? win_lo : win_hi) + (size_t)row * SRC_U4 + c * 6 + j;
            cpasync16(sptr(base + 2 * XS_U4 + arr * WS_U4 + row * 7 + j), src);
        }
    };

    float acc[2][4][4];
#pragma unroll
    for (int f = 0; f < 2; f++)
#pragma unroll
        for (int j = 0; j < 4; j++)
#pragma unroll
            for (int e = 0; e < 4; e++) acc[f][j][e] = 0.0f;

    prefetch(0, 0);
    asm volatile("cp.async.commit_group;");

    for (int c = 0; c < NCHUNK; c++) {
        int s = c & 1;
        if (c + 1 < NCHUNK) prefetch(c + 1, (c + 1) & 1);
        asm volatile("cp.async.commit_group;");
        asm volatile("cp.async.wait_group 1;");
        __syncthreads();

        const __nv_bfloat16* xs_hi = reinterpret_cast<const __nv_bfloat16*>(smem + s * STAGE_U4);
        const __nv_bfloat16* xs_lo = xs_hi + XS_U4 * 8;
        const __nv_bfloat16* ws_hi = xs_hi + 2 * XS_U4 * 8;
        const __nv_bfloat16* ws_lo = xs_hi + (2 * XS_U4 + WS_U4) * 8;

#pragma unroll
        for (int ks = 0; ks < CH / 16; ks++) {
            int k0 = ks * 16;
            uint32_t Ahi[2][4], Alo[2][4], Bhi[4][2], Blo[4][2];
#pragma unroll
            for (int f = 0; f < 2; f++) {
                int r = (a_row + f * 16) * KPS + k0 + a_kof;
                ldsm4(Ahi[f], sptr(&xs_hi[r]));
                ldsm4(Alo[f], sptr(&xs_lo[r]));
            }
#pragma unroll
            for (int jp = 0; jp < 2; jp++) {
                int r = (b_row + jp * 16) * KPS + k0 + b_kof;
                uint32_t t[4];
                ldsm4(t, sptr(&ws_hi[r]));
                Bhi[jp * 2][0] = t[0]; Bhi[jp * 2][1] = t[1];
                Bhi[jp * 2 + 1][0] = t[2]; Bhi[jp * 2 + 1][1] = t[3];
                ldsm4(t, sptr(&ws_lo[r]));
                Blo[jp * 2][0] = t[0]; Blo[jp * 2][1] = t[1];
                Blo[jp * 2 + 1][0] = t[2]; Blo[jp * 2 + 1][1] = t[3];
            }
#pragma unroll
            for (int f = 0; f < 2; f++)
#pragma unroll
                for (int j = 0; j < 4; j++) {
                    mma16816(acc[f][j], Ahi[f], Bhi[j]);
                    mma16816(acc[f][j], Ahi[f], Blo[j]);
                    mma16816(acc[f][j], Alo[f], Bhi[j]);
                }
        }
        __syncthreads();
    }

#pragma unroll
    for (int f = 0; f < 2; f++) {
        int rb = row0 + warp_m * 32 + f * 16 + g;
#pragma unroll
        for (int j = 0; j < 4; j++) {
            int col = warp_n * 32 + j * 8 + q * 2;
            if (rb < N)
                *reinterpret_cast<float2*>(&OUT[(size_t)rb * HID_DIM + col]) =
                    make_float2(acc[f][j][0], acc[f][j][1]);
            if (rb + 8 < N)
                *reinterpret_cast<float2*>(&OUT[(size_t)(rb + 8) * HID_DIM + col]) =
                    make_float2(acc[f][j][2], acc[f][j][3]);
        }
    }
}

// ------- CSR aggregation (node range): one warp per dst node -------
template <bool FINAL>
__global__ void __launch_bounds__(256) agg_kernel(const int* __restrict__ batch,
                                                  const float* __restrict__ bias,
                                                  int n0, int n1) {
    int node = n0 + ((blockIdx.x * blockDim.x + threadIdx.x) >> 5);
    int lane = threadIdx.x & 31;
    if (node >= n1) return;

    const float4* __restrict__ hs = reinterpret_cast<const float4*>(FINAL ? g_h2 : g_h1);
    float dsd = g_ds[node];
    float4 self = hs[(size_t)node * 32 + lane];
    float4 sum = make_float4(dsd * self.x, dsd * self.y, dsd * self.z, dsd * self.w);

    int start = g_rowstart[node];
    int deg = g_degi[node];

    for (int j0 = 0; j0 < deg; j0 += 32) {
        int idx = j0 + lane;
        int myid = (idx < deg) ? g_csrc[start + idx] : 0;
        float myds = g_ds[myid];
        int cnt = min(32, deg - j0);
#pragma unroll 4
        for (int k = 0; k < cnt; k++) {
            int s = __shfl_sync(0xffffffffu, myid, k);
            float dss = __shfl_sync(0xffffffffu, myds, k);
            float4 v = hs[(size_t)s * 32 + lane];
            sum.x = fmaf(dss, v.x, sum.x);
            sum.y = fmaf(dss, v.y, sum.y);
            sum.z = fmaf(dss, v.z, sum.z);
            sum.w = fmaf(dss, v.w, sum.w);
        }
    }

    float4 bv = reinterpret_cast<const float4*>(bias)[lane];
    float vx = fmaxf(fmaf(sum.x, dsd, bv.x), 0.0f);
    float vy = fmaxf(fmaf(sum.y, dsd, bv.y), 0.0f);
    float vz = fmaxf(fmaf(sum.z, dsd, bv.z), 0.0f);
    float vw = fmaxf(fmaf(sum.w, dsd, bv.w), 0.0f);

    if (!FINAL) {
        __nv_bfloat16 hx = __float2bfloat16(vx), hy = __float2bfloat16(vy);
        __nv_bfloat16 hz = __float2bfloat16(vz), hw = __float2bfloat16(vw);
        size_t base = (size_t)node * (KPW2 / 2);
        g_aghi[base + lane * 2] =
            (uint32_t)__bfloat16_as_ushort(hx) | ((uint32_t)__bfloat16_as_ushort(hy) << 16);
        g_aghi[base + lane * 2 + 1] =
            (uint32_t)__bfloat16_as_ushort(hz) | ((uint32_t)__bfloat16_as_ushort(hw) << 16);
        g_aglo[base + lane * 2] = packbf(vx - __bfloat162float(hx), vy - __bfloat162float(hy));
        g_aglo[base + lane * 2 + 1] = packbf(vz - __bfloat162float(hz), vw - __bfloat162float(hw));
        if (lane < 8) {
            g_aghi[base + 64 + lane] = 0u;
            g_aglo[base + 64 + lane] = 0u;
        }
    } else {
        float4* out = reinterpret_cast<float4*>(g_gsum) + batch[node] * 32 + lane;
        asm volatile("red.global.add.v4.f32 [%0], {%1, %2, %3, %4};"
                     :: "l"(out), "f"(vx), "f"(vy), "f"(vz), "f"(vw)
                     : "memory");
    }
}

// ---------------- FC head ----------------
__global__ void __launch_bounds__(64) fc_kernel(const float* __restrict__ Wf1,
                                                const float* __restrict__ bf1,
                                                const float* __restrict__ Wf2,
                                                const float* __restrict__ bf2,
                                                float* __restrict__ out) {
    __shared__ float grow[HID_DIM];
    __shared__ float a[FC_DIM];
    int g = blockIdx.x;
    int t = threadIdx.x;
    float inv = 1.0f / fmaxf(g_gcnt[g], 1.0f);
    grow[t] = g_gsum[g * HID_DIM + t] * inv;
    grow[t + 64] = g_gsum[g * HID_DIM + 64 + t] * inv;
    __syncthreads();
    float acc = bf1[t];
#pragma unroll 8
    for (int k = 0; k < HID_DIM; k++) acc += grow[k] * Wf1[k * FC_DIM + t];
    a[t] = fmaxf(acc, 0.0f);
    __syncthreads();
    if (t < OUT_DIM) {
        float o = bf2[t];
#pragma unroll 8
        for (int j = 0; j < FC_DIM; j++) o += a[j] * Wf2[j * OUT_DIM + t];
        out[g * OUT_DIM + t] = o;
    }
}

// ---------------- stream/event resources ----------------
struct Pipes {
    cudaStream_t sA = nullptr, sB = nullptr;
    cudaEvent_t fork = nullptr, evCSR = nullptr, evG1 = nullptr, evG2 = nullptr;
    cudaEvent_t evX[NCK] = {}, evA[NCK] = {};
    bool ok = false;
    Pipes() {
        if (cudaStreamCreateWithFlags(&sA, cudaStreamNonBlocking) != cudaSuccess) return;
        if (cudaStreamCreateWithFlags(&sB, cudaStreamNonBlocking) != cudaSuccess) return;
        if (cudaEventCreateWithFlags(&fork, cudaEventDisableTiming) != cudaSuccess) return;
        if (cudaEventCreateWithFlags(&evCSR, cudaEventDisableTiming) != cudaSuccess) return;
        if (cudaEventCreateWithFlags(&evG1, cudaEventDisableTiming) != cudaSuccess) return;
        if (cudaEventCreateWithFlags(&evG2, cudaEventDisableTiming) != cudaSuccess) return;
        for (int i = 0; i < NCK; i++) {
            if (cudaEventCreateWithFlags(&evX[i], cudaEventDisableTiming) != cudaSuccess) return;
            if (cudaEventCreateWithFlags(&evA[i], cudaEventDisableTiming) != cudaSuccess) return;
        }
        ok = true;
    }
};
static Pipes& pipes() { static Pipes p; return p; }

// ---------------- launcher ----------------
extern "C" void kernel_launch(void* const* d_in, const int* in_sizes, int n_in,
                              void* d_out, int out_size) {
    const float* x   = (const float*)d_in[0];
    const int* ei    = (const int*)d_in[1];
    const int* batch = (const int*)d_in[2];
    const float* W1  = (const float*)d_in[3];
    const float* b1  = (const float*)d_in[4];
    const float* W2  = (const float*)d_in[5];
    const float* b2  = (const float*)d_in[6];
    const float* Wf1 = (const float*)d_in[7];
    const float* bf1 = (const float*)d_in[8];
    const float* Wf2 = (const float*)d_in[9];
    const float* bf2 = (const float*)d_in[10];
    float* out = (float*)d_out;

    int E = in_sizes[1] / 2;
    int N = in_sizes[2];
    const int* src = ei;
    const int* dst = ei + E;
    int nb = (N_NODES + SCAN_BLK - 1) / SCAN_BLK;
    int totalblk = (N + 63) / 64;

    constexpr int SMEM_DYN = 2 * (2 * 64 * 7 + 2 * 128 * 7) * 16;   // 86016 B
    static bool attr_ok = false;
    if (!attr_ok) {
        cudaFuncSetAttribute(gemm_mma_kernel<5, 30, false>,
                             cudaFuncAttributeMaxDynamicSharedMemorySize, SMEM_DYN);
        cudaFuncSetAttribute(gemm_mma_kernel<3, 18, true>,
                             cudaFuncAttributeMaxDynamicSharedMemorySize, SMEM_DYN);
        attr_ok = true;
    }

    // chunk tables (64-row blocks)
    int cb[NCK], rb[NCK];
    for (int i = 0; i < NCK; i++) {
        rb[i] = i * CBLK * 64;
        int remain = totalblk - i * CBLK;
        cb[i] = remain > CBLK ? CBLK : (remain > 0 ? remain : 0);
    }

    Pipes& P = pipes();
    if (P.ok) {
        cudaEventRecord(P.fork, 0);
        cudaStreamWaitEvent(P.sA, P.fork, 0);
        cudaStreamWaitEvent(P.sB, P.fork, 0);

        // stream B: CSR build chain
        zero_kernel<<<(N_NODES + 255) / 256, 256, 0, P.sB>>>();
        hist_kernel<<<(E + 255) / 256, 256, 0, P.sB>>>(dst, E);
        scan1_kernel<<<nb, SCAN_BLK, 0, P.sB>>>();
        scan3_kernel<<<(N_NODES + 255) / 256, 256, 0, P.sB>>>(nb);
        scatter_kernel<<<(E + 255) / 256, 256, 0, P.sB>>>(src, dst, E);
        gcnt_kernel<<<1, N_GRAPHS, 0, P.sB>>>(batch, N);
        cudaEventRecord(P.evCSR, P.sB);

        // stream A: weight splits up front
        wsplit_kernel<false><<<(KPW1 * HID_DIM + 255) / 256, 256, 0, P.sA>>>(W1);
        wsplit_kernel<true><<<(KPW2 * HID_DIM + 255) / 256, 256, 0, P.sA>>>(W2);

        // main: xsplit chunks; stream A: GEMM1 chunk i after xsplit_i
        for (int i = 0; i < NCK; i++) {
            if (cb[i] == 0) continue;
            long long elems = (long long)cb[i] * 64 * (KPW1 / 2);
            xsplit_kernel<<<(int)((elems + 255) / 256), 256>>>(x, rb[i], cb[i] * 64, N);
            cudaEventRecord(P.evX[i], 0);
            cudaStreamWaitEvent(P.sA, P.evX[i], 0);
            gemm_mma_kernel<5, 30, false><<<cb[i], 256, SMEM_DYN, P.sA>>>(N, rb[i]);
        }
        cudaEventRecord(P.evG1, P.sA);

        // main: agg1 chunks (needs ALL of GEMM1 + CSR); stream A: GEMM2 chunk i after agg1_i
        cudaStreamWaitEvent(0, P.evG1, 0);
        cudaStreamWaitEvent(0, P.evCSR, 0);
        for (int i = 0; i < NCK; i++) {
            if (cb[i] == 0) continue;
            int n0 = rb[i];
            int n1 = rb[i] + cb[i] * 64; if (n1 > N) n1 = N;
            int warps = n1 - n0;
            agg_kernel<false><<<(int)(((long long)warps * 32 + 255) / 256), 256>>>(batch, b1, n0, n1);
            cudaEventRecord(P.evA[i], 0);
            cudaStreamWaitEvent(P.sA, P.evA[i], 0);
            gemm_mma_kernel<3, 18, true><<<cb[i], 256, SMEM_DYN, P.sA>>>(N, rb[i]);
        }
        cudaEventRecord(P.evG2, P.sA);
        cudaStreamWaitEvent(0, P.evG2, 0);

        agg_kernel<true><<<(int)(((long long)N * 32 + 255) / 256), 256>>>(batch, b2, 0, N);
        fc_kernel<<<N_GRAPHS, 64>>>(Wf1, bf1, Wf2, bf2, out);
    } else {
        // sequential fallback (identical math)
        zero_kernel<<<(N_NODES + 255) / 256, 256>>>();
        hist_kernel<<<(E + 255) / 256, 256>>>(dst, E);
        scan1_kernel<<<nb, SCAN_BLK>>>();
        scan3_kernel<<<(N_NODES + 255) / 256, 256>>>(nb);
        scatter_kernel<<<(E + 255) / 256, 256>>>(src, dst, E);
        gcnt_kernel<<<1, N_GRAPHS>>>(batch, N);
        wsplit_kernel<false><<<(KPW1 * HID_DIM + 255) / 256, 256>>>(W1);
        wsplit_kernel<true><<<(KPW2 * HID_DIM + 255) / 256, 256>>>(W2);
        xsplit_kernel<<<(int)(((long long)N * (KPW1 / 2) + 255) / 256), 256>>>(x, 0, totalblk * 64, N);
        gemm_mma_kernel<5, 30, false><<<totalblk, 256, SMEM_DYN>>>(N, 0);
        agg_kernel<false><<<(int)(((long long)N * 32 + 255) / 256), 256>>>(batch, b1, 0, N);
        gemm_mma_kernel<3, 18, true><<<totalblk, 256, SMEM_DYN>>>(N, 0);
        agg_kernel<true><<<(int)(((long long)N * 32 + 255) / 256), 256>>>(batch, b2, 0, N);
        fc_kernel<<<N_GRAPHS, 64>>>(Wf1, bf1, Wf2, bf2, out);
    }
}

// round 16
// speedup vs baseline: 1.1043x; 1.1043x over previous
#include <cuda_runtime.h>
#include <cuda_bf16.h>
#include <cuda_fp16.h>
#include <cstdint>
#include <cstring>

#define N_NODES   100000
#define N_PAD     100032    // rounded up to 64
#define N_EDGES_MAX 1600000
#define N_GRAPHS  256
#define IN_DIM    205
#define HID_DIM   128
#define FC_DIM    64
#define OUT_DIM   2
#define SCAN_BLK  1024

#define CH    48    // K-chunk per smem stage (3 MMA k-steps)
#define KPS   56    // smem row stride in bf16 (112B = 7*16B)
#define KPW1  240   // padded K for layer-1 (5 chunks), 30 uint4/row
#define KPW2  144   // padded K for layer-2 (3 chunks), 18 uint4/row

// ---------------- scratch (static device globals; referenced ONLY from device code) ----------------
__device__ __align__(128) __half g_h1[(size_t)N_PAD * HID_DIM];   // layer-1 GEMM output (fp16)
__device__ __align__(128) __half g_h2[(size_t)N_PAD * HID_DIM];   // layer-2 GEMM output (fp16)
__device__ __align__(128) uint32_t g_x1hi[(size_t)N_PAD * (KPW1 / 2)];  // X split hi (bf16 pairs)
__device__ __align__(128) uint32_t g_x1lo[(size_t)N_PAD * (KPW1 / 2)];
__device__ __align__(128) uint32_t g_aghi[(size_t)N_PAD * (KPW2 / 2)];  // relu(agg1+b1) split hi
__device__ __align__(128) uint32_t g_aglo[(size_t)N_PAD * (KPW2 / 2)];
__device__ int   g_degi[N_NODES];
__device__ int   g_rowstart[N_NODES];
__device__ int   g_cursor[N_NODES];
__device__ int   g_blocksum[128];
__device__ int   g_csrc[N_EDGES_MAX];
__device__ float g_ds[N_NODES];
__device__ float g_gsum[N_GRAPHS * HID_DIM];
__device__ float g_gcnt[N_GRAPHS];
// split-bf16 weights, [n][k_padded] layout
__device__ __align__(128) __nv_bfloat16 g_w1hi[HID_DIM * KPW1];
__device__ __align__(128) __nv_bfloat16 g_w1lo[HID_DIM * KPW1];
__device__ __align__(128) __nv_bfloat16 g_w2hi[HID_DIM * KPW2];
__device__ __align__(128) __nv_bfloat16 g_w2lo[HID_DIM * KPW2];

// ---------------- helpers ----------------
__device__ __forceinline__ uint32_t sptr(const void* p) {
    return (uint32_t)__cvta_generic_to_shared(p);
}
__device__ __forceinline__ void ldsm4(uint32_t* r, uint32_t addr) {
    asm volatile("ldmatrix.sync.aligned.m8n8.x4.shared.b16 {%0,%1,%2,%3}, [%4];"
                 : "=r"(r[0]), "=r"(r[1]), "=r"(r[2]), "=r"(r[3]) : "r"(addr));
}
__device__ __forceinline__ void mma16816(float* d, const uint32_t* a, const uint32_t* b) {
    asm volatile("mma.sync.aligned.m16n8k16.row.col.f32.bf16.bf16.f32 "
                 "{%0,%1,%2,%3}, {%4,%5,%6,%7}, {%8,%9}, {%0,%1,%2,%3};"
                 : "+f"(d[0]), "+f"(d[1]), "+f"(d[2]), "+f"(d[3])
                 : "r"(a[0]), "r"(a[1]), "r"(a[2]), "r"(a[3]), "r"(b[0]), "r"(b[1]));
}
__device__ __forceinline__ void cpasync16(uint32_t dst, const void* src) {
    asm volatile("cp.async.cg.shared.global [%0], [%1], 16;" :: "r"(dst), "l"(src));
}
__device__ __forceinline__ uint32_t packbf(float a, float b) {
    return (uint32_t)__bfloat16_as_ushort(__float2bfloat16(a)) |
           ((uint32_t)__bfloat16_as_ushort(__float2bfloat16(b)) << 16);
}

// ---------------- zero the small accumulators ----------------
__global__ void zero_kernel() {
    int i = blockIdx.x * blockDim.x + threadIdx.x;
    if (i < N_NODES) g_degi[i] = 0;
    if (i < N_GRAPHS * HID_DIM) g_gsum[i] = 0.0f;
}

// ---------------- X split: fp32 [N][205] -> bf16 hi/lo pairs [N][120 u32] ----------------
__global__ void xsplit_kernel(const float* __restrict__ X, int n) {
    int idx = blockIdx.x * blockDim.x + threadIdx.x;
    int total = n * (KPW1 / 2);
    if (idx >= total) return;
    int row = idx / (KPW1 / 2);
    int kp  = idx - row * (KPW1 / 2);
    int k0 = kp * 2;
    float v0 = (k0 < IN_DIM) ? X[(size_t)row * IN_DIM + k0] : 0.0f;
    float v1 = (k0 + 1 < IN_DIM) ? X[(size_t)row * IN_DIM + k0 + 1] : 0.0f;
    __nv_bfloat16 h0 = __float2bfloat16(v0), h1 = __float2bfloat16(v1);
    g_x1hi[idx] = (uint32_t)__bfloat16_as_ushort(h0) | ((uint32_t)__bfloat16_as_ushort(h1) << 16);
    g_x1lo[idx] = packbf(v0 - __bfloat162float(h0), v1 - __bfloat162float(h1));
}

// ---------------- weight split: W[K,128] -> hi/lo bf16 in [n][k_padded] ----------------
template <bool SECOND>
__global__ void wsplit_kernel(const float* __restrict__ W) {
    constexpr int K   = SECOND ? HID_DIM : IN_DIM;
    constexpr int KPW = SECOND ? KPW2 : KPW1;
    __nv_bfloat16* hi = SECOND ? g_w2hi : g_w1hi;
    __nv_bfloat16* lo = SECOND ? g_w2lo : g_w1lo;
    int idx = blockIdx.x * blockDim.x + threadIdx.x;
    if (idx >= KPW * HID_DIM) return;
    int kk = idx >> 7;
    int n  = idx & 127;
    float v = (kk < K) ? W[kk * HID_DIM + n] : 0.0f;
    __nv_bfloat16 h = __float2bfloat16(v);
    hi[n * KPW + kk] = h;
    lo[n * KPW + kk] = __float2bfloat16(v - __bfloat162float(h));
}

// ---------------- in-degree histogram ----------------
__global__ void hist_kernel(const int* __restrict__ dst, int E) {
    int e = blockIdx.x * blockDim.x + threadIdx.x;
    if (e < E) atomicAdd(&g_degi[dst[e]], 1);
}

// ---------------- scan level 1 ----------------
__global__ void scan1_kernel() {
    __shared__ int sh[SCAN_BLK];
    int i = blockIdx.x * SCAN_BLK + threadIdx.x;
    int v = (i < N_NODES) ? g_degi[i] : 0;
    sh[threadIdx.x] = v;
    __syncthreads();
    for (int off = 1; off < SCAN_BLK; off <<= 1) {
        int t = (threadIdx.x >= off) ? sh[threadIdx.x - off] : 0;
        __syncthreads();
        sh[threadIdx.x] += t;
        __syncthreads();
    }
    if (i < N_NODES) g_rowstart[i] = sh[threadIdx.x] - v;
    if (threadIdx.x == SCAN_BLK - 1) g_blocksum[blockIdx.x] = sh[threadIdx.x];
}

// -------- scan level 2 fused: parallel block-sum prefix; NO atomics --------
__global__ void scan3_kernel(int nb) {
    __shared__ int pref[256];
    int t = threadIdx.x;
    int v = (t < nb) ? g_blocksum[t] : 0;
    pref[t] = v;
    __syncthreads();
    for (int off = 1; off < 256; off <<= 1) {
        int u = (t >= off) ? pref[t - off] : 0;
        __syncthreads();
        pref[t] += u;
        __syncthreads();
    }
    int ex = pref[t] - v;
    __syncthreads();
    pref[t] = ex;
    __syncthreads();

    int i = blockIdx.x * blockDim.x + t;
    if (i >= N_NODES) return;
    int rs = g_rowstart[i] + pref[i / SCAN_BLK];
    g_rowstart[i] = rs;
    g_cursor[i] = rs;
    g_ds[i] = rsqrtf((float)g_degi[i] + 1.0f);
}

// ---------------- graph node counts via binary search on SORTED batch ----------------
__global__ void gcnt_kernel(const int* __restrict__ batch, int n) {
    __shared__ int lb[N_GRAPHS + 1];
    int g = threadIdx.x;
    int lo = 0, hi = n;
    while (lo < hi) {
        int mid = (lo + hi) >> 1;
        if (batch[mid] < g) lo = mid + 1; else hi = mid;
    }
    lb[g] = lo;
    if (g == 0) lb[N_GRAPHS] = n;
    __syncthreads();
    g_gcnt[g] = (float)(lb[g + 1] - lb[g]);
}

// ---------------- CSR scatter ----------------
__global__ void scatter_kernel(const int* __restrict__ src, const int* __restrict__ dst, int E) {
    int e = blockIdx.x * blockDim.x + threadIdx.x;
    if (e < E) {
        int pos = atomicAdd(&g_cursor[dst[e]], 1);
        g_csrc[pos] = src[e];
    }
}

// ---------------- split-bf16 MMA GEMM, cp.async double-buffered ----------------
// PRE=false: in = g_x1hi/lo (stride 30 u4), W = g_w1*, OUT = g_h1 (fp16).
// PRE=true : in = g_aghi/lo (stride 18 u4), W = g_w2*, OUT = g_h2 (fp16).
// CTA: 64 rows x 128 cols, 256 threads = 8 warps (2 M x 4 N), warp tile 32x32.
template <int NCHUNK, int SRC_U4, bool PRE>
__global__ void __launch_bounds__(256) gemm_mma_kernel(int N) {
    extern __shared__ __align__(128) uint4 smem[];
    constexpr int XS_U4 = 64 * 7;
    constexpr int WS_U4 = 128 * 7;
    constexpr int STAGE_U4 = 2 * XS_U4 + 2 * WS_U4;

    const uint4* xin_hi = reinterpret_cast<const uint4*>(PRE ? g_aghi : g_x1hi);
    const uint4* xin_lo = reinterpret_cast<const uint4*>(PRE ? g_aglo : g_x1lo);
    const uint4* win_hi = reinterpret_cast<const uint4*>(PRE ? g_w2hi : g_w1hi);
    const uint4* win_lo = reinterpret_cast<const uint4*>(PRE ? g_w2lo : g_w1lo);
    __half* OUT = PRE ? g_h2 : g_h1;

    int row0 = blockIdx.x * 64;
    int tid  = threadIdx.x;
    int lane = tid & 31;
    int warp = tid >> 5;
    int warp_m = warp & 1;
    int warp_n = warp >> 1;
    int g = lane >> 2;
    int q = lane & 3;

    int a_row = warp_m * 32 + (lane & 7) + ((lane >> 3) & 1) * 8;
    int a_kof = ((lane >> 4) & 1) * 8;
    int b_row = warp_n * 32 + (lane & 7) + ((lane >> 4) & 1) * 8;
    int b_kof = ((lane >> 3) & 1) * 8;

    auto prefetch = [&](int c, int s) {
        uint4* base = smem + s * STAGE_U4;
        for (int idx = tid; idx < 768; idx += 256) {
            int row = idx / 12;
            int r2 = idx - row * 12;
            int arr = r2 / 6;
            int j = r2 - arr * 6;
            const uint4* src = (arr ? xin_lo : xin_hi) + (size_t)(row0 + row) * SRC_U4 + c * 6 + j;
            cpasync16(sptr(base + arr * XS_U4 + row * 7 + j), src);
        }
        for (int idx = tid; idx < 1536; idx += 256) {
            int row = idx / 12;
            int r2 = idx - row * 12;
            int arr = r2 / 6;
            int j = r2 - arr * 6;
            const uint4* src = (arr ? win_lo : win_hi) + (size_t)row * SRC_U4 + c * 6 + j;
            cpasync16(sptr(base + 2 * XS_U4 + arr * WS_U4 + row * 7 + j), src);
        }
    };

    float acc[2][4][4];
#pragma unroll
    for (int f = 0; f < 2; f++)
#pragma unroll
        for (int j = 0; j < 4; j++)
#pragma unroll
            for (int e = 0; e < 4; e++) acc[f][j][e] = 0.0f;

    prefetch(0, 0);
    asm volatile("cp.async.commit_group;");

    for (int c = 0; c < NCHUNK; c++) {
        int s = c & 1;
        if (c + 1 < NCHUNK) prefetch(c + 1, (c + 1) & 1);
        asm volatile("cp.async.commit_group;");
        asm volatile("cp.async.wait_group 1;");
        __syncthreads();

        const __nv_bfloat16* xs_hi = reinterpret_cast<const __nv_bfloat16*>(smem + s * STAGE_U4);
        const __nv_bfloat16* xs_lo = xs_hi + XS_U4 * 8;
        const __nv_bfloat16* ws_hi = xs_hi + 2 * XS_U4 * 8;
        const __nv_bfloat16* ws_lo = xs_hi + (2 * XS_U4 + WS_U4) * 8;

#pragma unroll
        for (int ks = 0; ks < CH / 16; ks++) {
            int k0 = ks * 16;
            uint32_t Ahi[2][4], Alo[2][4], Bhi[4][2], Blo[4][2];
#pragma unroll
            for (int f = 0; f < 2; f++) {
                int r = (a_row + f * 16) * KPS + k0 + a_kof;
                ldsm4(Ahi[f], sptr(&xs_hi[r]));
                ldsm4(Alo[f], sptr(&xs_lo[r]));
            }
#pragma unroll
            for (int jp = 0; jp < 2; jp++) {
                int r = (b_row + jp * 16) * KPS + k0 + b_kof;
                uint32_t t[4];
                ldsm4(t, sptr(&ws_hi[r]));
                Bhi[jp * 2][0] = t[0]; Bhi[jp * 2][1] = t[1];
                Bhi[jp * 2 + 1][0] = t[2]; Bhi[jp * 2 + 1][1] = t[3];
                ldsm4(t, sptr(&ws_lo[r]));
                Blo[jp * 2][0] = t[0]; Blo[jp * 2][1] = t[1];
                Blo[jp * 2 + 1][0] = t[2]; Blo[jp * 2 + 1][1] = t[3];
            }
#pragma unroll
            for (int f = 0; f < 2; f++)
#pragma unroll
                for (int j = 0; j < 4; j++) {
                    mma16816(acc[f][j], Ahi[f], Bhi[j]);
                    mma16816(acc[f][j], Ahi[f], Blo[j]);
                    mma16816(acc[f][j], Alo[f], Bhi[j]);
                }
        }
        __syncthreads();
    }

    // epilogue: fragment -> global fp16 (half2 per pair)
#pragma unroll
    for (int f = 0; f < 2; f++) {
        int rb = row0 + warp_m * 32 + f * 16 + g;
#pragma unroll
        for (int j = 0; j < 4; j++) {
            int col = warp_n * 32 + j * 8 + q * 2;
            if (rb < N)
                *reinterpret_cast<__half2*>(&OUT[(size_t)rb * HID_DIM + col]) =
                    __floats2half2_rn(acc[f][j][0], acc[f][j][1]);
            if (rb + 8 < N)
                *reinterpret_cast<__half2*>(&OUT[(size_t)(rb + 8) * HID_DIM + col]) =
                    __floats2half2_rn(acc[f][j][2], acc[f][j][3]);
        }
    }
}

// ------- CSR aggregation over fp16 H: one warp per dst node; lane owns 4 features -------
// FINAL=false: relu(ds[d]*(sum ds[s]*H1[s] + ds[d]*H1[d]) + b1) -> split bf16 hi/lo [N][KPW2]
// FINAL=true : relu(same over H2 + b2) -> RED into g_gsum[batch[d]]
template <bool FINAL>
__global__ void __launch_bounds__(256) agg_kernel(const int* __restrict__ batch,
                                                  const float* __restrict__ bias,
                                                  int n) {
    int node = (blockIdx.x * blockDim.x + threadIdx.x) >> 5;
    int lane = threadIdx.x & 31;
    if (node >= n) return;

    const uint2* __restrict__ hs = reinterpret_cast<const uint2*>(FINAL ? g_h2 : g_h1);
    float dsd = g_ds[node];
    uint2 sv = hs[(size_t)node * 32 + lane];
    float2 s0 = __half22float2(*reinterpret_cast<__half2*>(&sv.x));
    float2 s1 = __half22float2(*reinterpret_cast<__half2*>(&sv.y));
    float4 sum = make_float4(dsd * s0.x, dsd * s0.y, dsd * s1.x, dsd * s1.y);

    int start = g_rowstart[node];
    int deg = g_degi[node];

    for (int j0 = 0; j0 < deg; j0 += 32) {
        int idx = j0 + lane;
        int myid = (idx < deg) ? g_csrc[start + idx] : 0;
        float myds = g_ds[myid];
        int cnt = min(32, deg - j0);
#pragma unroll 4
        for (int k = 0; k < cnt; k++) {
            int s = __shfl_sync(0xffffffffu, myid, k);
            float dss = __shfl_sync(0xffffffffu, myds, k);
            uint2 vv = hs[(size_t)s * 32 + lane];
            float2 v0 = __half22float2(*reinterpret_cast<__half2*>(&vv.x));
            float2 v1 = __half22float2(*reinterpret_cast<__half2*>(&vv.y));
            sum.x = fmaf(dss, v0.x, sum.x);
            sum.y = fmaf(dss, v0.y, sum.y);
            sum.z = fmaf(dss, v1.x, sum.z);
            sum.w = fmaf(dss, v1.y, sum.w);
        }
    }

    float4 bv = reinterpret_cast<const float4*>(bias)[lane];
    float vx = fmaxf(fmaf(sum.x, dsd, bv.x), 0.0f);
    float vy = fmaxf(fmaf(sum.y, dsd, bv.y), 0.0f);
    float vz = fmaxf(fmaf(sum.z, dsd, bv.z), 0.0f);
    float vw = fmaxf(fmaf(sum.w, dsd, bv.w), 0.0f);

    if (!FINAL) {
        __nv_bfloat16 hx = __float2bfloat16(vx), hy = __float2bfloat16(vy);
        __nv_bfloat16 hz = __float2bfloat16(vz), hw = __float2bfloat16(vw);
        size_t base = (size_t)node * (KPW2 / 2);
        g_aghi[base + lane * 2] =
            (uint32_t)__bfloat16_as_ushort(hx) | ((uint32_t)__bfloat16_as_ushort(hy) << 16);
        g_aghi[base + lane * 2 + 1] =
            (uint32_t)__bfloat16_as_ushort(hz) | ((uint32_t)__bfloat16_as_ushort(hw) << 16);
        g_aglo[base + lane * 2] = packbf(vx - __bfloat162float(hx), vy - __bfloat162float(hy));
        g_aglo[base + lane * 2 + 1] = packbf(vz - __bfloat162float(hz), vw - __bfloat162float(hw));
        if (lane < 8) {
            g_aghi[base + 64 + lane] = 0u;
            g_aglo[base + 64 + lane] = 0u;
        }
    } else {
        float4* out = reinterpret_cast<float4*>(g_gsum) + batch[node] * 32 + lane;
        asm volatile("red.global.add.v4.f32 [%0], {%1, %2, %3, %4};"
                     :: "l"(out), "f"(vx), "f"(vy), "f"(vz), "f"(vw)
                     : "memory");
    }
}

// ---------------- FC head ----------------
__global__ void __launch_bounds__(64) fc_kernel(const float* __restrict__ Wf1,
                                                const float* __restrict__ bf1,
                                                const float* __restrict__ Wf2,
                                                const float* __restrict__ bf2,
                                                float* __restrict__ out) {
    __shared__ float grow[HID_DIM];
    __shared__ float a[FC_DIM];
    int g = blockIdx.x;
    int t = threadIdx.x;
    float inv = 1.0f / fmaxf(g_gcnt[g], 1.0f);
    grow[t] = g_gsum[g * HID_DIM + t] * inv;
    grow[t + 64] = g_gsum[g * HID_DIM + 64 + t] * inv;
    __syncthreads();
    float acc = bf1[t];
#pragma unroll 8
    for (int k = 0; k < HID_DIM; k++) acc += grow[k] * Wf1[k * FC_DIM + t];
    a[t] = fmaxf(acc, 0.0f);
    __syncthreads();
    if (t < OUT_DIM) {
        float o = bf2[t];
#pragma unroll 8
        for (int j = 0; j < FC_DIM; j++) o += a[j] * Wf2[j * OUT_DIM + t];
        out[g * OUT_DIM + t] = o;
    }
}

// ---------------- fork/join resources ----------------
struct SideStream {
    cudaStream_t s = nullptr;
    cudaEvent_t fork = nullptr, join = nullptr;
    SideStream() {
        if (cudaStreamCreateWithFlags(&s, cudaStreamNonBlocking) != cudaSuccess) { s = nullptr; return; }
        if (cudaEventCreateWithFlags(&fork, cudaEventDisableTiming) != cudaSuccess) { s = nullptr; return; }
        if (cudaEventCreateWithFlags(&join, cudaEventDisableTiming) != cudaSuccess) { s = nullptr; return; }
    }
};
static SideStream& side() { static SideStream ss; return ss; }

// ---------------- launcher ----------------
extern "C" void kernel_launch(void* const* d_in, const int* in_sizes, int n_in,
                              void* d_out, int out_size) {
    const float* x   = (const float*)d_in[0];
    const int* ei    = (const int*)d_in[1];   // [2, E] int32
    const int* batch = (const int*)d_in[2];
    const float* W1  = (const float*)d_in[3];
    const float* b1  = (const float*)d_in[4];
    const float* W2  = (const float*)d_in[5];
    const float* b2  = (const float*)d_in[6];
    const float* Wf1 = (const float*)d_in[7];
    const float* bf1 = (const float*)d_in[8];
    const float* Wf2 = (const float*)d_in[9];
    const float* bf2 = (const float*)d_in[10];
    float* out = (float*)d_out;

    int E = in_sizes[1] / 2;
    int N = in_sizes[2];
    const int* src = ei;
    const int* dst = ei + E;
    int nb = (N_NODES + SCAN_BLK - 1) / SCAN_BLK;

    constexpr int SMEM_DYN = 2 * (2 * 64 * 7 + 2 * 128 * 7) * 16;   // 86016 B
    static bool attr_ok = false;
    if (!attr_ok) {
        cudaFuncSetAttribute(gemm_mma_kernel<5, 30, false>,
                             cudaFuncAttributeMaxDynamicSharedMemorySize, SMEM_DYN);
        cudaFuncSetAttribute(gemm_mma_kernel<3, 18, true>,
                             cudaFuncAttributeMaxDynamicSharedMemorySize, SMEM_DYN);
        attr_ok = true;
    }

    SideStream& ss = side();
    bool forked = (ss.s != nullptr);
    cudaStream_t cs = forked ? ss.s : (cudaStream_t)0;

    if (forked) {
        cudaEventRecord(ss.fork, 0);
        cudaStreamWaitEvent(ss.s, ss.fork, 0);
    }

    // --- CSR build chain (side stream): independent of GEMM1 ---
    zero_kernel<<<(N_NODES + 255) / 256, 256, 0, cs>>>();
    hist_kernel<<<(E + 255) / 256, 256, 0, cs>>>(dst, E);
    scan1_kernel<<<nb, SCAN_BLK, 0, cs>>>();
    scan3_kernel<<<(N_NODES + 255) / 256, 256, 0, cs>>>(nb);
    scatter_kernel<<<(E + 255) / 256, 256, 0, cs>>>(src, dst, E);
    gcnt_kernel<<<1, N_GRAPHS, 0, cs>>>(batch, N);
    if (forked) cudaEventRecord(ss.join, ss.s);

    // --- splits then GEMM1 -> g_h1 ---
    xsplit_kernel<<<(int)(((long long)N * (KPW1 / 2) + 255) / 256), 256>>>(x, N);
    wsplit_kernel<false><<<(KPW1 * HID_DIM + 255) / 256, 256>>>(W1);
    wsplit_kernel<true><<<(KPW2 * HID_DIM + 255) / 256, 256>>>(W2);
    gemm_mma_kernel<5, 30, false><<<(N + 63) / 64, 256, SMEM_DYN>>>(N);

    if (forked) cudaStreamWaitEvent(0, ss.join, 0);

    // --- layer-1 aggregation + b1 + relu -> split bf16 ---
    int agg_blocks = (int)(((long long)N * 32 + 255) / 256);
    agg_kernel<false><<<agg_blocks, 256>>>(batch, b1, N);

    // --- GEMM2 -> g_h2 ---
    gemm_mma_kernel<3, 18, true><<<(N + 63) / 64, 256, SMEM_DYN>>>(N);

    // --- layer-2 aggregation + b2 + relu + mean-pool accumulate ---
    agg_kernel<true><<<agg_blocks, 256>>>(batch, b2, N);

    fc_kernel<<<N_GRAPHS, 64>>>(Wf1, bf1, Wf2, bf2, out);
}

// round 17
// speedup vs baseline: 1.2468x; 1.1290x over previous
#include <cuda_runtime.h>
#include <cuda_bf16.h>
#include <cuda_fp16.h>
#include <cstdint>
#include <cstring>

#define N_NODES   100000
#define N_PAD     100032    // rounded up to 64
#define N_EDGES_MAX 1600000
#define N_GRAPHS  256
#define IN_DIM    205
#define HID_DIM   128
#define FC_DIM    64
#define OUT_DIM   2
#define SCAN_BLK  1024

#define CH    48    // K-chunk per smem stage (3 MMA k-steps)
#define KPS   56    // smem row stride in fp16 (112B = 7*16B)
#define KPW1  240   // padded K storage for layer-1 (5 chunks of 48); only 208 (13 steps) computed
#define KPW2  144   // padded K for layer-2 (3 chunks, 9 steps)

// ---------------- scratch (static device globals; referenced ONLY from device code) ----------------
__device__ __align__(128) __half g_h1[(size_t)N_PAD * HID_DIM];   // layer-1 GEMM output (fp16)
__device__ __align__(128) __half g_h2[(size_t)N_PAD * HID_DIM];   // layer-2 GEMM output (fp16)
__device__ __align__(128) uint32_t g_x1h[(size_t)N_PAD * (KPW1 / 2)];  // X as fp16 pairs
__device__ __align__(128) uint32_t g_agh[(size_t)N_PAD * (KPW2 / 2)];  // relu(agg1+b1) fp16 pairs
__device__ int   g_degi[N_NODES];
__device__ int   g_rowstart[N_NODES];
__device__ int   g_cursor[N_NODES];
__device__ int   g_blocksum[128];
__device__ int   g_csrc[N_EDGES_MAX];
__device__ float g_ds[N_NODES];
__device__ float g_gsum[N_GRAPHS * HID_DIM];
__device__ float g_gcnt[N_GRAPHS];
// split-fp16 weights (hi + lo = 22-bit effective), [n][k_padded] layout
__device__ __align__(128) __half g_w1hi[HID_DIM * KPW1];
__device__ __align__(128) __half g_w1lo[HID_DIM * KPW1];
__device__ __align__(128) __half g_w2hi[HID_DIM * KPW2];
__device__ __align__(128) __half g_w2lo[HID_DIM * KPW2];

// ---------------- helpers ----------------
__device__ __forceinline__ uint32_t sptr(const void* p) {
    return (uint32_t)__cvta_generic_to_shared(p);
}
__device__ __forceinline__ void ldsm4(uint32_t* r, uint32_t addr) {
    asm volatile("ldmatrix.sync.aligned.m8n8.x4.shared.b16 {%0,%1,%2,%3}, [%4];"
                 : "=r"(r[0]), "=r"(r[1]), "=r"(r[2]), "=r"(r[3]) : "r"(addr));
}
__device__ __forceinline__ void mma16816h(float* d, const uint32_t* a, const uint32_t* b) {
    asm volatile("mma.sync.aligned.m16n8k16.row.col.f32.f16.f16.f32 "
                 "{%0,%1,%2,%3}, {%4,%5,%6,%7}, {%8,%9}, {%0,%1,%2,%3};"
                 : "+f"(d[0]), "+f"(d[1]), "+f"(d[2]), "+f"(d[3])
                 : "r"(a[0]), "r"(a[1]), "r"(a[2]), "r"(a[3]), "r"(b[0]), "r"(b[1]));
}
__device__ __forceinline__ void cpasync16(uint32_t dst, const void* src) {
    asm volatile("cp.async.cg.shared.global [%0], [%1], 16;" :: "r"(dst), "l"(src));
}
__device__ __forceinline__ uint32_t packh2(float a, float b) {
    __half2 h = __floats2half2_rn(a, b);
    return *reinterpret_cast<uint32_t*>(&h);
}

// ---------------- zero the small accumulators ----------------
__global__ void zero_kernel() {
    int i = blockIdx.x * blockDim.x + threadIdx.x;
    if (i < N_NODES) g_degi[i] = 0;
    if (i < N_GRAPHS * HID_DIM) g_gsum[i] = 0.0f;
}

// ---------------- X convert: fp32 [N][205] -> fp16 pairs [N][120 u32] ----------------
__global__ void xsplit_kernel(const float* __restrict__ X, int n) {
    int idx = blockIdx.x * blockDim.x + threadIdx.x;
    int total = n * (KPW1 / 2);
    if (idx >= total) return;
    int row = idx / (KPW1 / 2);
    int kp  = idx - row * (KPW1 / 2);
    int k0 = kp * 2;
    float v0 = (k0 < IN_DIM) ? X[(size_t)row * IN_DIM + k0] : 0.0f;
    float v1 = (k0 + 1 < IN_DIM) ? X[(size_t)row * IN_DIM + k0 + 1] : 0.0f;
    g_x1h[idx] = packh2(v0, v1);
}

// ---------------- weight split: W[K,128] -> fp16 hi/lo in [n][k_padded] ----------------
template <bool SECOND>
__global__ void wsplit_kernel(const float* __restrict__ W) {
    constexpr int K   = SECOND ? HID_DIM : IN_DIM;
    constexpr int KPW = SECOND ? KPW2 : KPW1;
    __half* hi = SECOND ? g_w2hi : g_w1hi;
    __half* lo = SECOND ? g_w2lo : g_w1lo;
    int idx = blockIdx.x * blockDim.x + threadIdx.x;
    if (idx >= KPW * HID_DIM) return;
    int kk = idx >> 7;
    int n  = idx & 127;
    float v = (kk < K) ? W[kk * HID_DIM + n] : 0.0f;
    __half h = __float2half_rn(v);
    hi[n * KPW + kk] = h;
    lo[n * KPW + kk] = __float2half_rn(v - __half2float(h));
}

// ---------------- in-degree histogram ----------------
__global__ void hist_kernel(const int* __restrict__ dst, int E) {
    int e = blockIdx.x * blockDim.x + threadIdx.x;
    if (e < E) atomicAdd(&g_degi[dst[e]], 1);
}

// ---------------- scan level 1 ----------------
__global__ void scan1_kernel() {
    __shared__ int sh[SCAN_BLK];
    int i = blockIdx.x * SCAN_BLK + threadIdx.x;
    int v = (i < N_NODES) ? g_degi[i] : 0;
    sh[threadIdx.x] = v;
    __syncthreads();
    for (int off = 1; off < SCAN_BLK; off <<= 1) {
        int t = (threadIdx.x >= off) ? sh[threadIdx.x - off] : 0;
        __syncthreads();
        sh[threadIdx.x] += t;
        __syncthreads();
    }
    if (i < N_NODES) g_rowstart[i] = sh[threadIdx.x] - v;
    if (threadIdx.x == SCAN_BLK - 1) g_blocksum[blockIdx.x] = sh[threadIdx.x];
}

// -------- scan level 2 fused: parallel block-sum prefix; NO atomics --------
__global__ void scan3_kernel(int nb) {
    __shared__ int pref[256];
    int t = threadIdx.x;
    int v = (t < nb) ? g_blocksum[t] : 0;
    pref[t] = v;
    __syncthreads();
    for (int off = 1; off < 256; off <<= 1) {
        int u = (t >= off) ? pref[t - off] : 0;
        __syncthreads();
        pref[t] += u;
        __syncthreads();
    }
    int ex = pref[t] - v;
    __syncthreads();
    pref[t] = ex;
    __syncthreads();

    int i = blockIdx.x * blockDim.x + t;
    if (i >= N_NODES) return;
    int rs = g_rowstart[i] + pref[i / SCAN_BLK];
    g_rowstart[i] = rs;
    g_cursor[i] = rs;
    g_ds[i] = rsqrtf((float)g_degi[i] + 1.0f);
}

// ---------------- graph node counts via binary search on SORTED batch ----------------
__global__ void gcnt_kernel(const int* __restrict__ batch, int n) {
    __shared__ int lb[N_GRAPHS + 1];
    int g = threadIdx.x;
    int lo = 0, hi = n;
    while (lo < hi) {
        int mid = (lo + hi) >> 1;
        if (batch[mid] < g) lo = mid + 1; else hi = mid;
    }
    lb[g] = lo;
    if (g == 0) lb[N_GRAPHS] = n;
    __syncthreads();
    g_gcnt[g] = (float)(lb[g + 1] - lb[g]);
}

// ---------------- CSR scatter ----------------
__global__ void scatter_kernel(const int* __restrict__ src, const int* __restrict__ dst, int E) {
    int e = blockIdx.x * blockDim.x + threadIdx.x;
    if (e < E) {
        int pos = atomicAdd(&g_cursor[dst[e]], 1);
        g_csrc[pos] = src[e];
    }
}

// ---------------- fp16 2-product MMA GEMM, cp.async double-buffered ----------------
// A = fp16 activations (single), B = fp16 W hi + lo; acc += A*Bhi + A*Blo in fp32.
// PRE=false: in = g_x1h (stride 30 u4), W = g_w1*, OUT = g_h1.
// PRE=true : in = g_agh (stride 18 u4), W = g_w2*, OUT = g_h2.
// CTA: 64 rows x 128 cols, 256 threads = 8 warps (2 M x 4 N), warp tile 32x32.
// NSTEPS = real k-steps (16 wide); staged-but-dead steps are skipped.
template <int NCHUNK, int NSTEPS, int SRC_U4, bool PRE>
__global__ void __launch_bounds__(256) gemm_mma_kernel(int N) {
    extern __shared__ __align__(128) uint4 smem[];
    constexpr int XS_U4 = 64 * 7;
    constexpr int WS_U4 = 128 * 7;
    constexpr int STAGE_U4 = XS_U4 + 2 * WS_U4;   // 2240 u4 = 35840 B

    const uint4* xin = reinterpret_cast<const uint4*>(PRE ? g_agh : g_x1h);
    const uint4* win_hi = reinterpret_cast<const uint4*>(PRE ? g_w2hi : g_w1hi);
    const uint4* win_lo = reinterpret_cast<const uint4*>(PRE ? g_w2lo : g_w1lo);
    __half* OUT = PRE ? g_h2 : g_h1;

    int row0 = blockIdx.x * 64;
    int tid  = threadIdx.x;
    int lane = tid & 31;
    int warp = tid >> 5;
    int warp_m = warp & 1;
    int warp_n = warp >> 1;
    int g = lane >> 2;
    int q = lane & 3;

    int a_row = warp_m * 32 + (lane & 7) + ((lane >> 3) & 1) * 8;
    int a_kof = ((lane >> 4) & 1) * 8;
    int b_row = warp_n * 32 + (lane & 7) + ((lane >> 4) & 1) * 8;
    int b_kof = ((lane >> 3) & 1) * 8;

    auto prefetch = [&](int c, int s) {
        uint4* base = smem + s * STAGE_U4;
        for (int idx = tid; idx < 384; idx += 256) {          // A: 64 rows x 6 u4
            int row = idx / 6;
            int j = idx - row * 6;
            cpasync16(sptr(base + row * 7 + j),
                      xin + (size_t)(row0 + row) * SRC_U4 + c * 6 + j);
        }
        for (int idx = tid; idx < 1536; idx += 256) {         // B: 128 rows x 6 u4 x 2 arrays
            int row = idx / 12;
            int r2 = idx - row * 12;
            int arr = r2 / 6;
            int j = r2 - arr * 6;
            const uint4* src = (arr ? win_lo : win_hi) + (size_t)row * SRC_U4 + c * 6 + j;
            cpasync16(sptr(base + XS_U4 + arr * WS_U4 + row * 7 + j), src);
        }
    };

    float acc[2][4][4];
#pragma unroll
    for (int f = 0; f < 2; f++)
#pragma unroll
        for (int j = 0; j < 4; j++)
#pragma unroll
            for (int e = 0; e < 4; e++) acc[f][j][e] = 0.0f;

    prefetch(0, 0);
    asm volatile("cp.async.commit_group;");

    for (int c = 0; c < NCHUNK; c++) {
        int s = c & 1;
        if (c + 1 < NCHUNK) prefetch(c + 1, (c + 1) & 1);
        asm volatile("cp.async.commit_group;");
        asm volatile("cp.async.wait_group 1;");
        __syncthreads();

        const __half* xs = reinterpret_cast<const __half*>(smem + s * STAGE_U4);
        const __half* ws_hi = xs + XS_U4 * 8;
        const __half* ws_lo = xs + (XS_U4 + WS_U4) * 8;

        int lim = NSTEPS - c * 3;
        if (lim > 3) lim = 3;
#pragma unroll 3
        for (int ks = 0; ks < lim; ks++) {
            int k0 = ks * 16;
            uint32_t A[2][4], Bhi[4][2], Blo[4][2];
#pragma unroll
            for (int f = 0; f < 2; f++) {
                int r = (a_row + f * 16) * KPS + k0 + a_kof;
                ldsm4(A[f], sptr(&xs[r]));
            }
#pragma unroll
            for (int jp = 0; jp < 2; jp++) {
                int r = (b_row + jp * 16) * KPS + k0 + b_kof;
                uint32_t t[4];
                ldsm4(t, sptr(&ws_hi[r]));
                Bhi[jp * 2][0] = t[0]; Bhi[jp * 2][1] = t[1];
                Bhi[jp * 2 + 1][0] = t[2]; Bhi[jp * 2 + 1][1] = t[3];
                ldsm4(t, sptr(&ws_lo[r]));
                Blo[jp * 2][0] = t[0]; Blo[jp * 2][1] = t[1];
                Blo[jp * 2 + 1][0] = t[2]; Blo[jp * 2 + 1][1] = t[3];
            }
#pragma unroll
            for (int f = 0; f < 2; f++)
#pragma unroll
                for (int j = 0; j < 4; j++) {
                    mma16816h(acc[f][j], A[f], Bhi[j]);
                    mma16816h(acc[f][j], A[f], Blo[j]);
                }
        }
        __syncthreads();
    }

    // epilogue: fragment -> global fp16 (half2 per pair)
#pragma unroll
    for (int f = 0; f < 2; f++) {
        int rb = row0 + warp_m * 32 + f * 16 + g;
#pragma unroll
        for (int j = 0; j < 4; j++) {
            int col = warp_n * 32 + j * 8 + q * 2;
            if (rb < N)
                *reinterpret_cast<__half2*>(&OUT[(size_t)rb * HID_DIM + col]) =
                    __floats2half2_rn(acc[f][j][0], acc[f][j][1]);
            if (rb + 8 < N)
                *reinterpret_cast<__half2*>(&OUT[(size_t)(rb + 8) * HID_DIM + col]) =
                    __floats2half2_rn(acc[f][j][2], acc[f][j][3]);
        }
    }
}

// ------- CSR aggregation over fp16 H: one warp per dst node; lane owns 4 features -------
// FINAL=false: relu(ds[d]*(sum ds[s]*H1[s] + ds[d]*H1[d]) + b1) -> fp16 pairs g_agh
// FINAL=true : relu(same over H2 + b2) -> RED into g_gsum[batch[d]]
template <bool FINAL>
__global__ void __launch_bounds__(256) agg_kernel(const int* __restrict__ batch,
                                                  const float* __restrict__ bias,
                                                  int n) {
    int node = (blockIdx.x * blockDim.x + threadIdx.x) >> 5;
    int lane = threadIdx.x & 31;
    if (node >= n) return;

    const uint2* __restrict__ hs = reinterpret_cast<const uint2*>(FINAL ? g_h2 : g_h1);
    float dsd = g_ds[node];
    uint2 sv = hs[(size_t)node * 32 + lane];
    float2 s0 = __half22float2(*reinterpret_cast<__half2*>(&sv.x));
    float2 s1 = __half22float2(*reinterpret_cast<__half2*>(&sv.y));
    float4 sum = make_float4(dsd * s0.x, dsd * s0.y, dsd * s1.x, dsd * s1.y);

    int start = g_rowstart[node];
    int deg = g_degi[node];

    for (int j0 = 0; j0 < deg; j0 += 32) {
        int idx = j0 + lane;
        int myid = (idx < deg) ? g_csrc[start + idx] : 0;
        float myds = g_ds[myid];
        int cnt = min(32, deg - j0);
#pragma unroll 4
        for (int k = 0; k < cnt; k++) {
            int s = __shfl_sync(0xffffffffu, myid, k);
            float dss = __shfl_sync(0xffffffffu, myds, k);
            uint2 vv = hs[(size_t)s * 32 + lane];
            float2 v0 = __half22float2(*reinterpret_cast<__half2*>(&vv.x));
            float2 v1 = __half22float2(*reinterpret_cast<__half2*>(&vv.y));
            sum.x = fmaf(dss, v0.x, sum.x);
            sum.y = fmaf(dss, v0.y, sum.y);
            sum.z = fmaf(dss, v1.x, sum.z);
            sum.w = fmaf(dss, v1.y, sum.w);
        }
    }

    float4 bv = reinterpret_cast<const float4*>(bias)[lane];
    float vx = fmaxf(fmaf(sum.x, dsd, bv.x), 0.0f);
    float vy = fmaxf(fmaf(sum.y, dsd, bv.y), 0.0f);
    float vz = fmaxf(fmaf(sum.z, dsd, bv.z), 0.0f);
    float vw = fmaxf(fmaf(sum.w, dsd, bv.w), 0.0f);

    if (!FINAL) {
        size_t base = (size_t)node * (KPW2 / 2);
        g_agh[base + lane * 2] = packh2(vx, vy);
        g_agh[base + lane * 2 + 1] = packh2(vz, vw);
        if (lane < 8) g_agh[base + 64 + lane] = 0u;   // k-padding 128..143
    } else {
        float4* out = reinterpret_cast<float4*>(g_gsum) + batch[node] * 32 + lane;
        asm volatile("red.global.add.v4.f32 [%0], {%1, %2, %3, %4};"
                     :: "l"(out), "f"(vx), "f"(vy), "f"(vz), "f"(vw)
                     : "memory");
    }
}

// ---------------- FC head ----------------
__global__ void __launch_bounds__(64) fc_kernel(const float* __restrict__ Wf1,
                                                const float* __restrict__ bf1,
                                                const float* __restrict__ Wf2,
                                                const float* __restrict__ bf2,
                                                float* __restrict__ out) {
    __shared__ float grow[HID_DIM];
    __shared__ float a[FC_DIM];
    int g = blockIdx.x;
    int t = threadIdx.x;
    float inv = 1.0f / fmaxf(g_gcnt[g], 1.0f);
    grow[t] = g_gsum[g * HID_DIM + t] * inv;
    grow[t + 64] = g_gsum[g * HID_DIM + 64 + t] * inv;
    __syncthreads();
    float acc = bf1[t];
#pragma unroll 8
    for (int k = 0; k < HID_DIM; k++) acc += grow[k] * Wf1[k * FC_DIM + t];
    a[t] = fmaxf(acc, 0.0f);
    __syncthreads();
    if (t < OUT_DIM) {
        float o = bf2[t];
#pragma unroll 8
        for (int j = 0; j < FC_DIM; j++) o += a[j] * Wf2[j * OUT_DIM + t];
        out[g * OUT_DIM + t] = o;
    }
}

// ---------------- fork/join resources ----------------
struct SideStream {
    cudaStream_t s = nullptr;
    cudaEvent_t fork = nullptr, join = nullptr;
    SideStream() {
        if (cudaStreamCreateWithFlags(&s, cudaStreamNonBlocking) != cudaSuccess) { s = nullptr; return; }
        if (cudaEventCreateWithFlags(&fork, cudaEventDisableTiming) != cudaSuccess) { s = nullptr; return; }
        if (cudaEventCreateWithFlags(&join, cudaEventDisableTiming) != cudaSuccess) { s = nullptr; return; }
    }
};
static SideStream& side() { static SideStream ss; return ss; }

// ---------------- launcher ----------------
extern "C" void kernel_launch(void* const* d_in, const int* in_sizes, int n_in,
                              void* d_out, int out_size) {
    const float* x   = (const float*)d_in[0];
    const int* ei    = (const int*)d_in[1];   // [2, E] int32
    const int* batch = (const int*)d_in[2];
    const float* W1  = (const float*)d_in[3];
    const float* b1  = (const float*)d_in[4];
    const float* W2  = (const float*)d_in[5];
    const float* b2  = (const float*)d_in[6];
    const float* Wf1 = (const float*)d_in[7];
    const float* bf1 = (const float*)d_in[8];
    const float* Wf2 = (const float*)d_in[9];
    const float* bf2 = (const float*)d_in[10];
    float* out = (float*)d_out;

    int E = in_sizes[1] / 2;
    int N = in_sizes[2];
    const int* src = ei;
    const int* dst = ei + E;
    int nb = (N_NODES + SCAN_BLK - 1) / SCAN_BLK;

    constexpr int SMEM_DYN = 2 * (64 * 7 + 2 * 128 * 7) * 16;   // 71680 B
    static bool attr_ok = false;
    if (!attr_ok) {
        cudaFuncSetAttribute(gemm_mma_kernel<5, 13, 30, false>,
                             cudaFuncAttributeMaxDynamicSharedMemorySize, SMEM_DYN);
        cudaFuncSetAttribute(gemm_mma_kernel<3, 9, 18, true>,
                             cudaFuncAttributeMaxDynamicSharedMemorySize, SMEM_DYN);
        attr_ok = true;
    }

    SideStream& ss = side();
    bool forked = (ss.s != nullptr);
    cudaStream_t cs = forked ? ss.s : (cudaStream_t)0;

    if (forked) {
        cudaEventRecord(ss.fork, 0);
        cudaStreamWaitEvent(ss.s, ss.fork, 0);
    }

    // --- CSR build chain (side stream): independent of GEMM1 ---
    zero_kernel<<<(N_NODES + 255) / 256, 256, 0, cs>>>();
    hist_kernel<<<(E + 255) / 256, 256, 0, cs>>>(dst, E);
    scan1_kernel<<<nb, SCAN_BLK, 0, cs>>>();
    scan3_kernel<<<(N_NODES + 255) / 256, 256, 0, cs>>>(nb);
    scatter_kernel<<<(E + 255) / 256, 256, 0, cs>>>(src, dst, E);
    gcnt_kernel<<<1, N_GRAPHS, 0, cs>>>(batch, N);
    if (forked) cudaEventRecord(ss.join, ss.s);

    // --- converts then GEMM1 -> g_h1 ---
    xsplit_kernel<<<(int)(((long long)N * (KPW1 / 2) + 255) / 256), 256>>>(x, N);
    wsplit_kernel<false><<<(KPW1 * HID_DIM + 255) / 256, 256>>>(W1);
    wsplit_kernel<true><<<(KPW2 * HID_DIM + 255) / 256, 256>>>(W2);
    gemm_mma_kernel<5, 13, 30, false><<<(N + 63) / 64, 256, SMEM_DYN>>>(N);

    if (forked) cudaStreamWaitEvent(0, ss.join, 0);

    // --- layer-1 aggregation + b1 + relu -> fp16 ---
    int agg_blocks = (int)(((long long)N * 32 + 255) / 256);
    agg_kernel<false><<<agg_blocks, 256>>>(batch, b1, N);

    // --- GEMM2 -> g_h2 ---
    gemm_mma_kernel<3, 9, 18, true><<<(N + 63) / 64, 256, SMEM_DYN>>>(N);

    // --- layer-2 aggregation + b2 + relu + mean-pool accumulate ---
    agg_kernel<true><<<agg_blocks, 256>>>(batch, b2, N);

    fc_kernel<<<N_GRAPHS, 64>>>(Wf1, bf1, Wf2, bf2, out);
}